// round 10
// baseline (speedup 1.0000x reference)
#include <cuda_runtime.h>

#define BB 8
#define CC 64
#define NN 400
#define NN2 (NN * NN)          // 160000
#define NV4 (NN / 4)           // 100
#define TT 16                  // tile dim (400 = 25*16 exact)
#define NT 25                  // tiles per dim
#define NPAIR 300              // off-diagonal unordered pairs r<s
#define PPB (NPAIR + NT)       // 325 blocks per batch (300 pairs + 25 diagonal)
#define KT 32                  // k-tile width in epilogue

// Scratch (device globals: no allocation allowed in kernel_launch)
__device__ float g_xp[NT * BB * CC * NN];  // partial x by source n-tile (20.5 MB)
__device__ float g_x [BB * CC * NN];       // reduced x                  (0.82 MB)

// ---------------------------------------------------------------------------
// max-pass: stream tile (rowt, colt) of R (all 64 ch), channel-max only,
// publish f-tile apub[j*TT+i] = relu(tanh(max_c R[b,c,rowt*16+i,colt*16+j])).
// ---------------------------------------------------------------------------
__device__ __forceinline__ void max_pass(const float* __restrict__ R, int b,
                                         int rowt, int colt,
                                         float* cm, float* apub, int tid) {
    const int chain = tid >> 6;           // 0..3 -> channels chain*16..+15
    const int p     = tid & 63;
    const int nl    = p >> 2;             // local row 0..15
    const int k4    = p & 3;              // col quad 0..3

    const float* base = R + (size_t)(b * CC + chain * 16) * NN2
                          + (size_t)(rowt * TT + nl) * NN + colt * TT + k4 * 4;
    float4 mx = *reinterpret_cast<const float4*>(base);
    #pragma unroll
    for (int ci = 1; ci < 16; ++ci) {
        float4 v = *reinterpret_cast<const float4*>(base + (size_t)ci * NN2);
        mx.x = fmaxf(mx.x, v.x); mx.y = fmaxf(mx.y, v.y);
        mx.z = fmaxf(mx.z, v.z); mx.w = fmaxf(mx.w, v.w);
    }
    *reinterpret_cast<float4*>(cm + (chain * 64 + p) * 4) = mx;
    __syncthreads();

    if (tid < 64) {
        float4 m0 = *reinterpret_cast<float4*>(cm + (0 * 64 + tid) * 4);
        float4 m1 = *reinterpret_cast<float4*>(cm + (1 * 64 + tid) * 4);
        float4 m2 = *reinterpret_cast<float4*>(cm + (2 * 64 + tid) * 4);
        float4 m3 = *reinterpret_cast<float4*>(cm + (3 * 64 + tid) * 4);
        float4 m;
        m.x = fmaxf(fmaxf(m0.x, m1.x), fmaxf(m2.x, m3.x));
        m.y = fmaxf(fmaxf(m0.y, m1.y), fmaxf(m2.y, m3.y));
        m.z = fmaxf(fmaxf(m0.z, m1.z), fmaxf(m2.z, m3.z));
        m.w = fmaxf(fmaxf(m0.w, m1.w), fmaxf(m2.w, m3.w));
        int i  = tid >> 2;                // local row
        int jq = (tid & 3) * 4;           // local col quad
        apub[(jq + 0) * TT + i] = (m.x > 0.f) ? tanhf(m.x) : 0.f;
        apub[(jq + 1) * TT + i] = (m.y > 0.f) ? tanhf(m.y) : 0.f;
        apub[(jq + 2) * TT + i] = (m.z > 0.f) ? tanhf(m.z) : 0.f;
        apub[(jq + 3) * TT + i] = (m.w > 0.f) ? tanhf(m.w) : 0.f;
    }
    __syncthreads();   // apub ready; cm free for reuse
}

// ---------------------------------------------------------------------------
// acc-pass: re-read tile (rt, ct) (L2-hot) and write
//   xp[rt][b][c][k in ct] = sum_n R[b,c,rt*16+n,ct*16+k] * a[n*TT+k]
// where a must be the f-tile of R-tile (ct, rt), i.e. a[n][k]=A[b,ct*16+k,rt*16+n].
// ---------------------------------------------------------------------------
__device__ __forceinline__ void acc_pass(const float* __restrict__ R, int b,
                                         int rt, int ct,
                                         const float* a, int tid) {
    const int c  = tid >> 2;              // 0..63
    const int kg = (tid & 3) * 4;         // k quad base
    const float* rb = R + (size_t)(b * CC + c) * NN2
                        + (size_t)(rt * TT) * NN + ct * TT + kg;
    float4 acc = make_float4(0.f, 0.f, 0.f, 0.f);
    #pragma unroll
    for (int n = 0; n < TT; ++n) {
        float4 r = *reinterpret_cast<const float4*>(rb + (size_t)n * NN);
        float4 av = *reinterpret_cast<const float4*>(a + n * TT + kg);
        acc.x = fmaf(r.x, av.x, acc.x);
        acc.y = fmaf(r.y, av.y, acc.y);
        acc.z = fmaf(r.z, av.z, acc.z);
        acc.w = fmaf(r.w, av.w, acc.w);
    }
    *reinterpret_cast<float4*>(
        g_xp + (((size_t)rt * BB + b) * CC + c) * NN + ct * TT + kg) = acc;
}

// ---------------------------------------------------------------------------
// Fused single-DRAM-read kernel, v3: ONE block owns tile pair (r,s)+(s,r).
// No clusters, no DSMEM, no inter-CTA sync. apub layouts line up so each
// acc-pass directly consumes the other tile's f-tile.
// ---------------------------------------------------------------------------
__global__ void __launch_bounds__(256, 6) kfused3(const float* __restrict__ R) {
    __shared__ float cm[4 * 64 * 4];      // per-chain maxes: 4 KB
    __shared__ float apub1[TT * TT];      // f-tile of (r,s): 1 KB
    __shared__ float apub2[TT * TT];      // f-tile of (s,r): 1 KB

    const int idx   = blockIdx.x;
    const int b     = idx / PPB;
    const int local = idx - b * PPB;
    const int tid   = threadIdx.x;

    if (local < NPAIR) {
        int r = 0, rem = local;
        while (rem >= (NT - 1) - r) { rem -= (NT - 1) - r; ++r; }
        int s = r + 1 + rem;

        max_pass(R, b, r, s, cm, apub1, tid);   // f-tile of (r,s)
        max_pass(R, b, s, r, cm, apub2, tid);   // f-tile of (s,r)
        acc_pass(R, b, s, r, apub1, tid);       // tile (s,r) hottest; needs apub_of(r,s)
        acc_pass(R, b, r, s, apub2, tid);       // needs apub_of(s,r)
    } else {
        int d = local - NPAIR;                  // diagonal tile
        max_pass(R, b, d, d, cm, apub1, tid);
        acc_pass(R, b, d, d, apub1, tid);
    }
}

// ---------------------------------------------------------------------------
// k3a (R9 verbatim): g_x = sum over 25 slots of g_xp.
// ---------------------------------------------------------------------------
__global__ void k3a_reduce() {
    const int total4 = BB * CC * NV4;                  // 51200
    int t = blockIdx.x * blockDim.x + threadIdx.x;
    if (t >= total4) return;
    const float4* xp4 = reinterpret_cast<const float4*>(g_xp);
    const int stride4 = BB * CC * NV4;

    float4 s0 = xp4[t];
    float4 s1 = xp4[(size_t)1 * stride4 + t];
    float4 s2 = xp4[(size_t)2 * stride4 + t];
    float4 s3 = xp4[(size_t)3 * stride4 + t];
    #pragma unroll
    for (int slot = 4; slot + 3 < NT; slot += 4) {
        float4 v0 = xp4[(size_t)(slot + 0) * stride4 + t];
        float4 v1 = xp4[(size_t)(slot + 1) * stride4 + t];
        float4 v2 = xp4[(size_t)(slot + 2) * stride4 + t];
        float4 v3 = xp4[(size_t)(slot + 3) * stride4 + t];
        s0.x += v0.x; s0.y += v0.y; s0.z += v0.z; s0.w += v0.w;
        s1.x += v1.x; s1.y += v1.y; s1.z += v1.z; s1.w += v1.w;
        s2.x += v2.x; s2.y += v2.y; s2.z += v2.z; s2.w += v2.w;
        s3.x += v3.x; s3.y += v3.y; s3.z += v3.z; s3.w += v3.w;
    }
    {
        float4 v = xp4[(size_t)24 * stride4 + t];
        s0.x += v.x; s0.y += v.y; s0.z += v.z; s0.w += v.w;
    }
    float4 s;
    s.x = (s0.x + s1.x) + (s2.x + s3.x);
    s.y = (s0.y + s1.y) + (s2.y + s3.y);
    s.z = (s0.z + s1.z) + (s2.z + s3.z);
    s.w = (s0.w + s1.w) + (s2.w + s3.w);
    reinterpret_cast<float4*>(g_x)[t] = s;
}

// ---------------------------------------------------------------------------
// k3b (R4 verbatim): out[b,o,k] = sum_c W[o,c] * x[b,c,k] + bias[o]
// ---------------------------------------------------------------------------
__global__ void k3b_linear(const float* __restrict__ W,
                           const float* __restrict__ bias,
                           float* __restrict__ out) {
    __shared__ float xs[CC][KT + 1];
    const int b  = blockIdx.z;
    const int og = blockIdx.y;
    const int k0 = blockIdx.x * KT;
    const int x  = threadIdx.x;
    const int y  = threadIdx.y;
    const int k  = k0 + x;
    const bool valid = (k < NN);
    const int kc = valid ? k : (NN - 1);

    for (int c = y; c < CC; c += 8)
        xs[c][x] = g_x[((size_t)b * CC + c) * NN + kc];
    __syncthreads();

    #pragma unroll
    for (int oi = 0; oi < 2; ++oi) {
        int o = og * 16 + y + oi * 8;
        float acc = bias[o];
        const float* wr = W + o * CC;
        #pragma unroll 16
        for (int c = 0; c < CC; ++c)
            acc = fmaf(wr[c], xs[c][x], acc);
        if (valid)
            out[((size_t)b * CC + o) * NN + k] = acc;
    }
}

// ---------------------------------------------------------------------------
extern "C" void kernel_launch(void* const* d_in, const int* in_sizes, int n_in,
                              void* d_out, int out_size) {
    const float* R    = (const float*)d_in[0];
    const float* W    = (const float*)d_in[1];
    const float* bias = (const float*)d_in[2];
    float*       out  = (float*)d_out;

    // Fused single-read kernel: 8 * 325 = 2600 plain blocks (no clusters)
    kfused3<<<BB * PPB, 256>>>(R);

    // k3a: 25-slot partial reduce (200 blocks)
    {
        int total4 = BB * CC * NV4;
        k3a_reduce<<<(total4 + 255) / 256, 256>>>();
    }

    // k3b: linear (416 blocks)
    {
        dim3 grid((NN + KT - 1) / KT, 4, BB);
        dim3 blk(32, 8);
        k3b_linear<<<grid, blk>>>(W, bias, out);
    }
}